// round 2
// baseline (speedup 1.0000x reference)
#include <cuda_runtime.h>
#include <cstdint>

// Problem constants
#define NEXP   8
#define DDIM   1024
#define IDIM   2048
#define KTOP   2
#define NTOK   4096               // B*S
#define NASN   (NTOK * KTOP)      // 8192 assignments

// ---------------- device scratch (no allocations allowed) ----------------
__device__ int   g_is64;
__device__ int   g_count[NEXP];
__device__ int   g_offset[NEXP];
__device__ int   g_tok[NASN];
__device__ float g_wt[NASN];
__device__ float g_h[(size_t)NASN * IDIM];   // 64 MB intermediate activations

// ---------------- helpers ----------------
__device__ __forceinline__ uint32_t f32_to_tf32(float x) {
    uint32_t r;
    asm("cvt.rna.tf32.f32 %0, %1;" : "=r"(r) : "f"(x));
    return r;
}

__device__ __forceinline__ void mma_tf32(float* c, const uint32_t* a, const uint32_t* b) {
    asm volatile(
        "mma.sync.aligned.m16n8k8.row.col.f32.tf32.tf32.f32 "
        "{%0,%1,%2,%3}, {%4,%5,%6,%7}, {%8,%9}, {%0,%1,%2,%3};\n"
        : "+f"(c[0]), "+f"(c[1]), "+f"(c[2]), "+f"(c[3])
        : "r"(a[0]), "r"(a[1]), "r"(a[2]), "r"(a[3]),
          "r"(b[0]), "r"(b[1]));
}

// Fetch expert id for assignment i, handling int32 vs int64 wire format.
__device__ __forceinline__ int get_expert(const int* se32, int i) {
    int v = g_is64 ? se32[2 * i] : se32[i];   // little-endian low word for int64
    return v & (NEXP - 1);
}

// ---------------- dtype detection ----------------
// If se is int64 with values 0..7, odd 32-bit words (high words) are all zero.
// If se is int32 uniform 0..7, P(128 odd words all zero) = 8^-128 ~ 0.
__global__ void detect_dtype_kernel(const int* __restrict__ se32) {
    if (threadIdx.x == 0) {
        int nz = 0;
        #pragma unroll 8
        for (int i = 1; i < 256; i += 2) nz |= se32[i];
        g_is64 = (nz == 0) ? 1 : 0;
    }
}

// ---------------- routing ----------------
__global__ void zero_out_kernel(float4* out, int n4) {
    int i = blockIdx.x * blockDim.x + threadIdx.x;
    if (blockIdx.x == 0 && threadIdx.x < NEXP) g_count[threadIdx.x] = 0;
    if (i < n4) out[i] = make_float4(0.f, 0.f, 0.f, 0.f);
}

__global__ void route_count_kernel(const int* __restrict__ se32) {
    int i = blockIdx.x * blockDim.x + threadIdx.x;
    if (i < NASN) {
        int e = get_expert(se32, i);
        atomicAdd(&g_count[e], 1);
    }
}

__global__ void route_scan_kernel() {
    if (threadIdx.x == 0) {
        int off = 0;
        for (int e = 0; e < NEXP; e++) {
            g_offset[e] = off;
            off += g_count[e];
        }
    }
}

// Deterministic stable placement: single block, chunked counting sort.
__global__ void route_place_kernel(const int* __restrict__ se32,
                                   const float* __restrict__ rw) {
    __shared__ int base[NEXP];
    __shared__ unsigned char ebuf[256];
    int tid = threadIdx.x;
    if (tid < NEXP) base[tid] = g_offset[tid];
    __syncthreads();
    for (int chunk = 0; chunk < NASN / 256; chunk++) {
        int i = chunk * 256 + tid;
        int e = get_expert(se32, i);
        ebuf[tid] = (unsigned char)e;
        __syncthreads();
        int rank = 0;
        for (int j = 0; j < tid; j++) rank += (ebuf[j] == e);
        int pos = base[e] + rank;
        g_tok[pos] = i / KTOP;
        g_wt[pos]  = rw[i];
        __syncthreads();
        if (tid < NEXP) {
            int c = 0;
            #pragma unroll 8
            for (int j = 0; j < 256; j++) c += (ebuf[j] == tid);
            base[tid] += c;
        }
        __syncthreads();
    }
}

// ---------------- grouped GEMM (tf32 mma.sync, 128x64x32 tiles) ----------------
// SECOND == false : h = silu(X_gathered @ w1_e)  -> g_h
// SECOND == true  : out[tok] += (g_h @ w2_e) * wt  (atomicAdd)
template <int KDIM, int NDIM, bool SECOND>
__global__ __launch_bounds__(256, 2)
void moe_gemm(const float* __restrict__ Xin,
              const float* __restrict__ Wglob,
              float* __restrict__ Oglob) {
    constexpr int BM = 128, BN = 64, BK = 32;
    constexpr int ASTR = 36;
    constexpr int BSTR = 72;

    extern __shared__ float smem[];
    float* As = smem;                       // [2][BM][ASTR]
    float* Bs = smem + 2 * BM * ASTR;       // [2][BK][BSTR]

    const int e   = blockIdx.z;
    const int cnt = g_count[e];
    if ((int)blockIdx.y * BM >= cnt) return;

    const int off     = g_offset[e];
    const int rowBase = off + blockIdx.y * BM;   // global assignment row
    const int rowEnd  = off + cnt;
    const int nBase   = blockIdx.x * BN;
    const float* Wp   = Wglob + (size_t)e * KDIM * NDIM;

    const int tid  = threadIdx.x;
    const int lane = tid & 31;
    const int warp = tid >> 5;
    const int gq   = lane >> 2;   // groupID
    const int tig  = lane & 3;    // thread in group
    const int wm   = (warp & 3) * 32;
    const int wn   = (warp >> 2) * 32;

    // Per-thread A row pointers (gather for GEMM1, direct for GEMM2)
    const float* arow[4];
    int acol[4];
    #pragma unroll
    for (int j = 0; j < 4; j++) {
        int item = tid + j * 256;
        int r    = item >> 3;            // 0..127
        acol[j]  = (item & 7) * 4;
        int grow = rowBase + r;
        if (grow < rowEnd) {
            if (SECOND) arow[j] = g_h + (size_t)grow * KDIM;
            else        arow[j] = Xin + (size_t)g_tok[grow] * KDIM;
        } else {
            arow[j] = nullptr;
        }
    }

    float acc[2][4][4];
    #pragma unroll
    for (int mt = 0; mt < 2; mt++)
        #pragma unroll
        for (int nt = 0; nt < 4; nt++)
            #pragma unroll
            for (int q = 0; q < 4; q++) acc[mt][nt][q] = 0.f;

    float4 areg[4], breg[2];

    auto load_global = [&](int kb) {
        #pragma unroll
        for (int j = 0; j < 4; j++) {
            if (arow[j]) areg[j] = *(const float4*)(arow[j] + kb * BK + acol[j]);
            else         areg[j] = make_float4(0.f, 0.f, 0.f, 0.f);
        }
        #pragma unroll
        for (int j = 0; j < 2; j++) {
            int item = tid + j * 256;
            int r = item >> 4;                 // 0..31
            int c = (item & 15) * 4;           // 0..60
            breg[j] = *(const float4*)(Wp + (size_t)(kb * BK + r) * NDIM + nBase + c);
        }
    };

    auto store_smem = [&](int buf) {
        float* Ab = As + buf * BM * ASTR;
        float* Bb = Bs + buf * BK * BSTR;
        #pragma unroll
        for (int j = 0; j < 4; j++) {
            int item = tid + j * 256;
            int r = item >> 3;
            int c = (item & 7) * 4;
            float4 v = areg[j];
            v.x = __uint_as_float(f32_to_tf32(v.x));
            v.y = __uint_as_float(f32_to_tf32(v.y));
            v.z = __uint_as_float(f32_to_tf32(v.z));
            v.w = __uint_as_float(f32_to_tf32(v.w));
            *(float4*)(Ab + r * ASTR + c) = v;
        }
        #pragma unroll
        for (int j = 0; j < 2; j++) {
            int item = tid + j * 256;
            int r = item >> 4;
            int c = (item & 15) * 4;
            float4 v = breg[j];
            v.x = __uint_as_float(f32_to_tf32(v.x));
            v.y = __uint_as_float(f32_to_tf32(v.y));
            v.z = __uint_as_float(f32_to_tf32(v.z));
            v.w = __uint_as_float(f32_to_tf32(v.w));
            *(float4*)(Bb + r * BSTR + c) = v;
        }
    };

    auto compute = [&](int buf) {
        const float* Ab = As + buf * BM * ASTR;
        const float* Bb = Bs + buf * BK * BSTR;
        #pragma unroll
        for (int ks = 0; ks < 4; ks++) {
            int k0 = ks * 8;
            uint32_t a[2][4];
            #pragma unroll
            for (int mt = 0; mt < 2; mt++) {
                int r = wm + mt * 16 + gq;
                a[mt][0] = __float_as_uint(Ab[r * ASTR + k0 + tig]);
                a[mt][1] = __float_as_uint(Ab[(r + 8) * ASTR + k0 + tig]);
                a[mt][2] = __float_as_uint(Ab[r * ASTR + k0 + tig + 4]);
                a[mt][3] = __float_as_uint(Ab[(r + 8) * ASTR + k0 + tig + 4]);
            }
            uint32_t b[4][2];
            #pragma unroll
            for (int nt = 0; nt < 4; nt++) {
                int cN = wn + nt * 8 + gq;
                b[nt][0] = __float_as_uint(Bb[(k0 + tig) * BSTR + cN]);
                b[nt][1] = __float_as_uint(Bb[(k0 + tig + 4) * BSTR + cN]);
            }
            #pragma unroll
            for (int mt = 0; mt < 2; mt++)
                #pragma unroll
                for (int nt = 0; nt < 4; nt++)
                    mma_tf32(acc[mt][nt], a[mt], b[nt]);
        }
    };

    load_global(0);
    store_smem(0);
    __syncthreads();

    const int NKB = KDIM / BK;
    for (int kb = 0; kb < NKB; ++kb) {
        if (kb + 1 < NKB) load_global(kb + 1);
        compute(kb & 1);
        if (kb + 1 < NKB) store_smem((kb + 1) & 1);
        __syncthreads();
    }

    // Epilogue
    #pragma unroll
    for (int mt = 0; mt < 2; mt++) {
        #pragma unroll
        for (int half = 0; half < 2; half++) {
            int rloc = wm + mt * 16 + gq + half * 8;
            int grow = rowBase + rloc;
            if (grow >= rowEnd) continue;
            if (SECOND) {
                int   tok = g_tok[grow];
                float wgt = g_wt[grow];
                float* orow = Oglob + (size_t)tok * NDIM + nBase;
                #pragma unroll
                for (int nt = 0; nt < 4; nt++) {
                    int cc = wn + nt * 8 + tig * 2;
                    float v0 = acc[mt][nt][half * 2 + 0];
                    float v1 = acc[mt][nt][half * 2 + 1];
                    atomicAdd(&orow[cc],     v0 * wgt);
                    atomicAdd(&orow[cc + 1], v1 * wgt);
                }
            } else {
                float* hrow = g_h + (size_t)grow * NDIM + nBase;
                #pragma unroll
                for (int nt = 0; nt < 4; nt++) {
                    int cc = wn + nt * 8 + tig * 2;
                    float v0 = acc[mt][nt][half * 2 + 0];
                    float v1 = acc[mt][nt][half * 2 + 1];
                    hrow[cc]     = v0 / (1.f + __expf(-v0));   // silu
                    hrow[cc + 1] = v1 / (1.f + __expf(-v1));
                }
            }
        }
    }
}

// ---------------- launch ----------------
extern "C" void kernel_launch(void* const* d_in, const int* in_sizes, int n_in,
                              void* d_out, int out_size) {
    const float* x    = (const float*)d_in[0];
    const float* rw   = (const float*)d_in[1];
    const int*   se32 = (const int*)d_in[2];
    const float* w1   = (const float*)d_in[3];
    const float* w2   = (const float*)d_in[4];
    float*       out  = (float*)d_out;

    constexpr int SMEM_BYTES = (2 * 128 * 36 + 2 * 32 * 72) * 4;  // 55296

    cudaFuncSetAttribute((const void*)moe_gemm<DDIM, IDIM, false>,
                         cudaFuncAttributeMaxDynamicSharedMemorySize, SMEM_BYTES);
    cudaFuncSetAttribute((const void*)moe_gemm<IDIM, DDIM, true>,
                         cudaFuncAttributeMaxDynamicSharedMemorySize, SMEM_BYTES);

    int n4 = out_size / 4;
    detect_dtype_kernel<<<1, 32>>>(se32);
    zero_out_kernel<<<(n4 + 255) / 256, 256>>>((float4*)out, n4);
    route_count_kernel<<<(NASN + 255) / 256, 256>>>(se32);
    route_scan_kernel<<<1, 32>>>();
    route_place_kernel<<<1, 256>>>(se32, rw);

    dim3 g1(IDIM / 64, NASN / 128, NEXP);   // (32, 64, 8)
    moe_gemm<DDIM, IDIM, false><<<g1, 256, SMEM_BYTES>>>(x, w1, out);

    dim3 g2(DDIM / 64, NASN / 128, NEXP);   // (16, 64, 8)
    moe_gemm<IDIM, DDIM, true><<<g2, 256, SMEM_BYTES>>>(x, w2, out);
}

// round 5
// speedup vs baseline: 1.0061x; 1.0061x over previous
#include <cuda_runtime.h>
#include <cstdint>

// Problem constants
#define NEXP   8
#define DDIM   1024
#define IDIM   2048
#define KTOP   2
#define NTOK   4096               // B*S
#define NASN   (NTOK * KTOP)      // 8192 assignments

// ---------------- device scratch (no allocations allowed) ----------------
__device__ int   g_is64;
__device__ int   g_count[NEXP];
__device__ int   g_offset[NEXP];
__device__ int   g_tok[NASN];
__device__ float g_wt[NASN];
__device__ float g_h[(size_t)NASN * IDIM];   // 64 MB intermediate activations

// ---------------- helpers ----------------
__device__ __forceinline__ uint32_t f32_to_tf32(float x) {
    uint32_t r;
    asm("cvt.rna.tf32.f32 %0, %1;" : "=r"(r) : "f"(x));
    return r;
}

__device__ __forceinline__ void mma_tf32(float* c, const uint32_t* a, const uint32_t* b) {
    asm volatile(
        "mma.sync.aligned.m16n8k8.row.col.f32.tf32.tf32.f32 "
        "{%0,%1,%2,%3}, {%4,%5,%6,%7}, {%8,%9}, {%0,%1,%2,%3};\n"
        : "+f"(c[0]), "+f"(c[1]), "+f"(c[2]), "+f"(c[3])
        : "r"(a[0]), "r"(a[1]), "r"(a[2]), "r"(a[3]),
          "r"(b[0]), "r"(b[1]));
}

// Fetch expert id for assignment i, handling int32 vs int64 wire format.
__device__ __forceinline__ int get_expert(const int* se32, int i) {
    int v = g_is64 ? se32[2 * i] : se32[i];   // little-endian low word for int64
    return v & (NEXP - 1);
}

// ---------------- dtype detection + zero ----------------
__global__ void zero_out_kernel(float4* out, int n4, const int* __restrict__ se32) {
    int i = blockIdx.x * blockDim.x + threadIdx.x;
    if (blockIdx.x == 0 && threadIdx.x < NEXP) g_count[threadIdx.x] = 0;
    if (blockIdx.x == 0 && threadIdx.x == 0) {
        int nz = 0;
        #pragma unroll 8
        for (int j = 1; j < 256; j += 2) nz |= se32[j];
        g_is64 = (nz == 0) ? 1 : 0;
    }
    if (i < n4) out[i] = make_float4(0.f, 0.f, 0.f, 0.f);
}

// ---------------- routing ----------------
__global__ void route_count_kernel(const int* __restrict__ se32) {
    int i = blockIdx.x * blockDim.x + threadIdx.x;
    if (i < NASN) {
        int e = get_expert(se32, i);
        atomicAdd(&g_count[e], 1);
    }
}

__global__ void route_scan_kernel() {
    if (threadIdx.x == 0) {
        int off = 0;
        for (int e = 0; e < NEXP; e++) {
            g_offset[e] = off;
            off += g_count[e];
        }
    }
}

// Deterministic stable placement: single block, chunked counting sort (proven in R2).
__global__ void route_place_kernel(const int* __restrict__ se32,
                                   const float* __restrict__ rw) {
    __shared__ int base[NEXP];
    __shared__ unsigned char ebuf[256];
    int tid = threadIdx.x;
    if (tid < NEXP) base[tid] = g_offset[tid];
    __syncthreads();
    for (int chunk = 0; chunk < NASN / 256; chunk++) {
        int i = chunk * 256 + tid;
        int e = get_expert(se32, i);
        ebuf[tid] = (unsigned char)e;
        __syncthreads();
        int rank = 0;
        for (int j = 0; j < tid; j++) rank += (ebuf[j] == e);
        int pos = base[e] + rank;
        g_tok[pos] = i / KTOP;
        g_wt[pos]  = rw[i];
        __syncthreads();
        if (tid < NEXP) {
            int c = 0;
            #pragma unroll 8
            for (int j = 0; j < 256; j++) c += (ebuf[j] == tid);
            base[tid] += c;
        }
        __syncthreads();
    }
}

// ---------------- grouped GEMM (tf32 mma.sync, 128x128x32 tiles, dbl-buffered) ----------------
// SECOND == false : h = silu(X_gathered @ w1_e)  -> g_h
// SECOND == true  : out[tok] += (g_h @ w2_e) * wt  (atomicAdd)
template <int KDIM, int NDIM, bool SECOND>
__global__ __launch_bounds__(256)
void moe_gemm(const float* __restrict__ Xin,
              const float* __restrict__ Wglob,
              float* __restrict__ Oglob) {
    constexpr int BM = 128, BN = 128, BK = 32;
    constexpr int ASTR = 36;    // 36 mod 32 == 4 -> conflict-free A frag LDS
    constexpr int BSTR = 136;   // 136 mod 32 == 8 -> conflict-free B frag LDS

    extern __shared__ float smem[];
    float* As = smem;                       // [2][BM][ASTR]
    float* Bs = smem + 2 * BM * ASTR;       // [2][BK][BSTR]

    const int e   = blockIdx.z;
    const int cnt = g_count[e];
    if ((int)blockIdx.y * BM >= cnt) return;

    const int off     = g_offset[e];
    const int rowBase = off + blockIdx.y * BM;   // global assignment row
    const int rowEnd  = off + cnt;
    const int nBase   = blockIdx.x * BN;
    const float* Wp   = Wglob + (size_t)e * KDIM * NDIM;

    const int tid  = threadIdx.x;
    const int lane = tid & 31;
    const int warp = tid >> 5;
    const int gq   = lane >> 2;          // groupID 0..7
    const int tig  = lane & 3;           // thread-in-group 0..3
    const int wm   = (warp >> 1) * 32;   // 4 warp-rows of 32
    const int wn   = (warp & 1) * 64;    // 2 warp-cols of 64

    // Per-thread A row pointers (gather for GEMM1, direct for GEMM2)
    const float* arow[4];
    int acol[4];
    #pragma unroll
    for (int j = 0; j < 4; j++) {
        int item = tid + j * 256;
        int r    = item >> 3;            // 0..127
        acol[j]  = (item & 7) * 4;
        int grow = rowBase + r;
        if (grow < rowEnd) {
            if (SECOND) arow[j] = g_h + (size_t)grow * KDIM;
            else        arow[j] = Xin + (size_t)g_tok[grow] * KDIM;
        } else {
            arow[j] = nullptr;
        }
    }

    float acc[2][8][4];
    #pragma unroll
    for (int mt = 0; mt < 2; mt++)
        #pragma unroll
        for (int nt = 0; nt < 8; nt++)
            #pragma unroll
            for (int q = 0; q < 4; q++) acc[mt][nt][q] = 0.f;

    float4 areg[4], breg[4];

    auto load_global = [&](int kb) {
        #pragma unroll
        for (int j = 0; j < 4; j++) {
            if (arow[j]) areg[j] = *(const float4*)(arow[j] + kb * BK + acol[j]);
            else         areg[j] = make_float4(0.f, 0.f, 0.f, 0.f);
        }
        #pragma unroll
        for (int j = 0; j < 4; j++) {
            int item = tid + j * 256;
            int r = item >> 5;                 // k row 0..31
            int c = (item & 31) * 4;           // col 0..124
            breg[j] = *(const float4*)(Wp + (size_t)(kb * BK + r) * NDIM + nBase + c);
        }
    };

    auto store_smem = [&](int buf) {
        float* Ab = As + buf * BM * ASTR;
        float* Bb = Bs + buf * BK * BSTR;
        #pragma unroll
        for (int j = 0; j < 4; j++) {
            int item = tid + j * 256;
            int r = item >> 3;
            int c = (item & 7) * 4;
            float4 v = areg[j];
            v.x = __uint_as_float(f32_to_tf32(v.x));
            v.y = __uint_as_float(f32_to_tf32(v.y));
            v.z = __uint_as_float(f32_to_tf32(v.z));
            v.w = __uint_as_float(f32_to_tf32(v.w));
            *(float4*)(Ab + r * ASTR + c) = v;
        }
        #pragma unroll
        for (int j = 0; j < 4; j++) {
            int item = tid + j * 256;
            int r = item >> 5;
            int c = (item & 31) * 4;
            float4 v = breg[j];
            v.x = __uint_as_float(f32_to_tf32(v.x));
            v.y = __uint_as_float(f32_to_tf32(v.y));
            v.z = __uint_as_float(f32_to_tf32(v.z));
            v.w = __uint_as_float(f32_to_tf32(v.w));
            *(float4*)(Bb + r * BSTR + c) = v;
        }
    };

    auto compute = [&](int buf) {
        const float* Ab = As + buf * BM * ASTR;
        const float* Bb = Bs + buf * BK * BSTR;
        #pragma unroll
        for (int ks = 0; ks < 4; ks++) {
            int k0 = ks * 8;
            uint32_t a[2][4];
            #pragma unroll
            for (int mt = 0; mt < 2; mt++) {
                int r = wm + mt * 16 + gq;
                a[mt][0] = __float_as_uint(Ab[r * ASTR + k0 + tig]);
                a[mt][1] = __float_as_uint(Ab[(r + 8) * ASTR + k0 + tig]);
                a[mt][2] = __float_as_uint(Ab[r * ASTR + k0 + tig + 4]);
                a[mt][3] = __float_as_uint(Ab[(r + 8) * ASTR + k0 + tig + 4]);
            }
            #pragma unroll
            for (int nt = 0; nt < 8; nt++) {
                int cN = wn + nt * 8 + gq;
                uint32_t b[2];
                b[0] = __float_as_uint(Bb[(k0 + tig) * BSTR + cN]);
                b[1] = __float_as_uint(Bb[(k0 + tig + 4) * BSTR + cN]);
                mma_tf32(acc[0][nt], a[0], b);
                mma_tf32(acc[1][nt], a[1], b);
            }
        }
    };

    load_global(0);
    store_smem(0);
    __syncthreads();

    const int NKB = KDIM / BK;
    for (int kb = 0; kb < NKB; ++kb) {
        if (kb + 1 < NKB) load_global(kb + 1);
        compute(kb & 1);
        if (kb + 1 < NKB) store_smem((kb + 1) & 1);
        __syncthreads();
    }

    // ---------------- epilogue ----------------
    #pragma unroll
    for (int mt = 0; mt < 2; mt++) {
        #pragma unroll
        for (int half = 0; half < 2; half++) {
            int rloc = wm + mt * 16 + gq + half * 8;
            int grow = rowBase + rloc;
            if (grow >= rowEnd) continue;
            if (SECOND) {
                const int   tok = g_tok[grow];
                const float wgt = g_wt[grow];
                float* orow = Oglob + (size_t)tok * NDIM + nBase;
                #pragma unroll
                for (int nt = 0; nt < 8; nt++) {
                    int cc = wn + nt * 8 + tig * 2;
                    atomicAdd(&orow[cc],     acc[mt][nt][half * 2 + 0] * wgt);
                    atomicAdd(&orow[cc + 1], acc[mt][nt][half * 2 + 1] * wgt);
                }
            } else {
                float* hrow = g_h + (size_t)grow * NDIM + nBase;
                #pragma unroll
                for (int nt = 0; nt < 8; nt++) {
                    int cc = wn + nt * 8 + tig * 2;
                    float v0 = acc[mt][nt][half * 2 + 0];
                    float v1 = acc[mt][nt][half * 2 + 1];
                    hrow[cc]     = v0 / (1.f + __expf(-v0));   // silu
                    hrow[cc + 1] = v1 / (1.f + __expf(-v1));
                }
            }
        }
    }
}

// ---------------- launch ----------------
extern "C" void kernel_launch(void* const* d_in, const int* in_sizes, int n_in,
                              void* d_out, int out_size) {
    const float* x    = (const float*)d_in[0];
    const float* rw   = (const float*)d_in[1];
    const int*   se32 = (const int*)d_in[2];
    const float* w1   = (const float*)d_in[3];
    const float* w2   = (const float*)d_in[4];
    float*       out  = (float*)d_out;

    constexpr int SMEM_BYTES = (2 * 128 * 36 + 2 * 32 * 136) * 4;  // 71680

    cudaFuncSetAttribute((const void*)moe_gemm<DDIM, IDIM, false>,
                         cudaFuncAttributeMaxDynamicSharedMemorySize, SMEM_BYTES);
    cudaFuncSetAttribute((const void*)moe_gemm<IDIM, DDIM, true>,
                         cudaFuncAttributeMaxDynamicSharedMemorySize, SMEM_BYTES);

    int n4 = out_size / 4;
    zero_out_kernel<<<(n4 + 255) / 256, 256>>>((float4*)out, n4, se32);
    route_count_kernel<<<(NASN + 255) / 256, 256>>>(se32);
    route_scan_kernel<<<1, 32>>>();
    route_place_kernel<<<1, 256>>>(se32, rw);

    dim3 g1(IDIM / 128, NASN / 128, NEXP);   // (16, 64, 8)
    moe_gemm<DDIM, IDIM, false><<<g1, 256, SMEM_BYTES>>>(x, w1, out);

    dim3 g2(DDIM / 128, NASN / 128, NEXP);   // (8, 64, 8)
    moe_gemm<IDIM, DDIM, true><<<g2, 256, SMEM_BYTES>>>(g_h, w2, out);
}

// round 7
// speedup vs baseline: 1.1533x; 1.1463x over previous
#include <cuda_runtime.h>
#include <cstdint>

// Problem constants
#define NEXP   8
#define DDIM   1024
#define IDIM   2048
#define KTOP   2
#define NTOK   4096               // B*S
#define NASN   (NTOK * KTOP)      // 8192 assignments

// ---------------- device scratch (no allocations allowed) ----------------
__device__ int   g_is64;
__device__ int   g_count[NEXP];
__device__ int   g_offset[NEXP];
__device__ int   g_tok[NASN];
__device__ float g_wt[NASN];
__device__ float g_h[(size_t)NASN * IDIM];   // 64 MB intermediate activations

// ---------------- helpers ----------------
__device__ __forceinline__ uint32_t f32_to_tf32(float x) {
    uint32_t r;
    asm("cvt.rna.tf32.f32 %0, %1;" : "=r"(r) : "f"(x));
    return r;
}

__device__ __forceinline__ void mma_tf32(float* c, const uint32_t* a, const uint32_t* b) {
    asm volatile(
        "mma.sync.aligned.m16n8k8.row.col.f32.tf32.tf32.f32 "
        "{%0,%1,%2,%3}, {%4,%5,%6,%7}, {%8,%9}, {%0,%1,%2,%3};\n"
        : "+f"(c[0]), "+f"(c[1]), "+f"(c[2]), "+f"(c[3])
        : "r"(a[0]), "r"(a[1]), "r"(a[2]), "r"(a[3]),
          "r"(b[0]), "r"(b[1]));
}

// Fetch expert id for assignment i, handling int32 vs int64 wire format.
__device__ __forceinline__ int get_expert(const int* se32, int i) {
    int v = g_is64 ? se32[2 * i] : se32[i];   // little-endian low word for int64
    return v & (NEXP - 1);
}

// ---------------- dtype detection + zero ----------------
__global__ void zero_out_kernel(float4* out, int n4, const int* __restrict__ se32) {
    int i = blockIdx.x * blockDim.x + threadIdx.x;
    if (blockIdx.x == 0 && threadIdx.x == 0) {
        int nz = 0;
        #pragma unroll 8
        for (int j = 1; j < 256; j += 2) nz |= se32[j];
        g_is64 = (nz == 0) ? 1 : 0;
    }
    if (i < n4) out[i] = make_float4(0.f, 0.f, 0.f, 0.f);
}

// ---------------- routing: warp-per-expert ballot scan (deterministic, stable) ----------------
__global__ void route_kernel(const int* __restrict__ se32, const float* __restrict__ rw) {
    const int tid  = threadIdx.x;
    const int warp = tid >> 5;          // warp w owns expert w
    const int lane = tid & 31;
    const unsigned lt = (1u << lane) - 1u;   // lanes below me (lane=0 -> 0)

    // pass 1: count my expert
    int cnt = 0;
    for (int it = 0; it < NASN / 32; it++) {
        int i = it * 32 + lane;
        unsigned m = __ballot_sync(0xFFFFFFFFu, get_expert(se32, i) == warp);
        cnt += __popc(m);
    }
    if (lane == 0) g_count[warp] = cnt;
    __syncthreads();
    if (tid == 0) {
        int off = 0;
        for (int e = 0; e < NEXP; e++) { g_offset[e] = off; off += g_count[e]; }
    }
    __syncthreads();

    // pass 2: stable placement (order = assignment index, same as counting sort)
    int base = g_offset[warp];
    for (int it = 0; it < NASN / 32; it++) {
        int i = it * 32 + lane;
        bool mine = (get_expert(se32, i) == warp);
        unsigned m = __ballot_sync(0xFFFFFFFFu, mine);
        if (mine) {
            int r = __popc(m & lt);
            g_tok[base + r] = i / KTOP;
            g_wt[base + r]  = rw[i];
        }
        base += __popc(m);
    }
}

// ---------------- grouped GEMM (tf32 mma.sync, 128x128x32 tiles, dbl-buffered) ----------------
// (byte-identical to the R5-passing version)
// SECOND == false : h = silu(X_gathered @ w1_e)  -> g_h
// SECOND == true  : out[tok] += (g_h @ w2_e) * wt  (atomicAdd)
template <int KDIM, int NDIM, bool SECOND>
__global__ __launch_bounds__(256)
void moe_gemm(const float* __restrict__ Xin,
              const float* __restrict__ Wglob,
              float* __restrict__ Oglob) {
    constexpr int BM = 128, BN = 128, BK = 32;
    constexpr int ASTR = 36;    // 36 mod 32 == 4 -> conflict-free A frag LDS
    constexpr int BSTR = 136;   // 136 mod 32 == 8 -> conflict-free B frag LDS

    extern __shared__ float smem[];
    float* As = smem;                       // [2][BM][ASTR]
    float* Bs = smem + 2 * BM * ASTR;       // [2][BK][BSTR]

    const int e   = blockIdx.z;
    const int cnt = g_count[e];
    if ((int)blockIdx.y * BM >= cnt) return;

    const int off     = g_offset[e];
    const int rowBase = off + blockIdx.y * BM;   // global assignment row
    const int rowEnd  = off + cnt;
    const int nBase   = blockIdx.x * BN;
    const float* Wp   = Wglob + (size_t)e * KDIM * NDIM;

    const int tid  = threadIdx.x;
    const int lane = tid & 31;
    const int warp = tid >> 5;
    const int gq   = lane >> 2;          // groupID 0..7
    const int tig  = lane & 3;           // thread-in-group 0..3
    const int wm   = (warp >> 1) * 32;   // 4 warp-rows of 32
    const int wn   = (warp & 1) * 64;    // 2 warp-cols of 64

    // Per-thread A row pointers (gather for GEMM1, direct for GEMM2)
    const float* arow[4];
    int acol[4];
    #pragma unroll
    for (int j = 0; j < 4; j++) {
        int item = tid + j * 256;
        int r    = item >> 3;            // 0..127
        acol[j]  = (item & 7) * 4;
        int grow = rowBase + r;
        if (grow < rowEnd) {
            if (SECOND) arow[j] = g_h + (size_t)grow * KDIM;
            else        arow[j] = Xin + (size_t)g_tok[grow] * KDIM;
        } else {
            arow[j] = nullptr;
        }
    }

    float acc[2][8][4];
    #pragma unroll
    for (int mt = 0; mt < 2; mt++)
        #pragma unroll
        for (int nt = 0; nt < 8; nt++)
            #pragma unroll
            for (int q = 0; q < 4; q++) acc[mt][nt][q] = 0.f;

    float4 areg[4], breg[4];

    auto load_global = [&](int kb) {
        #pragma unroll
        for (int j = 0; j < 4; j++) {
            if (arow[j]) areg[j] = *(const float4*)(arow[j] + kb * BK + acol[j]);
            else         areg[j] = make_float4(0.f, 0.f, 0.f, 0.f);
        }
        #pragma unroll
        for (int j = 0; j < 4; j++) {
            int item = tid + j * 256;
            int r = item >> 5;                 // k row 0..31
            int c = (item & 31) * 4;           // col 0..124
            breg[j] = *(const float4*)(Wp + (size_t)(kb * BK + r) * NDIM + nBase + c);
        }
    };

    auto store_smem = [&](int buf) {
        float* Ab = As + buf * BM * ASTR;
        float* Bb = Bs + buf * BK * BSTR;
        #pragma unroll
        for (int j = 0; j < 4; j++) {
            int item = tid + j * 256;
            int r = item >> 3;
            int c = (item & 7) * 4;
            float4 v = areg[j];
            v.x = __uint_as_float(f32_to_tf32(v.x));
            v.y = __uint_as_float(f32_to_tf32(v.y));
            v.z = __uint_as_float(f32_to_tf32(v.z));
            v.w = __uint_as_float(f32_to_tf32(v.w));
            *(float4*)(Ab + r * ASTR + c) = v;
        }
        #pragma unroll
        for (int j = 0; j < 4; j++) {
            int item = tid + j * 256;
            int r = item >> 5;
            int c = (item & 31) * 4;
            float4 v = breg[j];
            v.x = __uint_as_float(f32_to_tf32(v.x));
            v.y = __uint_as_float(f32_to_tf32(v.y));
            v.z = __uint_as_float(f32_to_tf32(v.z));
            v.w = __uint_as_float(f32_to_tf32(v.w));
            *(float4*)(Bb + r * BSTR + c) = v;
        }
    };

    auto compute = [&](int buf) {
        const float* Ab = As + buf * BM * ASTR;
        const float* Bb = Bs + buf * BK * BSTR;
        #pragma unroll
        for (int ks = 0; ks < 4; ks++) {
            int k0 = ks * 8;
            uint32_t a[2][4];
            #pragma unroll
            for (int mt = 0; mt < 2; mt++) {
                int r = wm + mt * 16 + gq;
                a[mt][0] = __float_as_uint(Ab[r * ASTR + k0 + tig]);
                a[mt][1] = __float_as_uint(Ab[(r + 8) * ASTR + k0 + tig]);
                a[mt][2] = __float_as_uint(Ab[r * ASTR + k0 + tig + 4]);
                a[mt][3] = __float_as_uint(Ab[(r + 8) * ASTR + k0 + tig + 4]);
            }
            #pragma unroll
            for (int nt = 0; nt < 8; nt++) {
                int cN = wn + nt * 8 + gq;
                uint32_t b[2];
                b[0] = __float_as_uint(Bb[(k0 + tig) * BSTR + cN]);
                b[1] = __float_as_uint(Bb[(k0 + tig + 4) * BSTR + cN]);
                mma_tf32(acc[0][nt], a[0], b);
                mma_tf32(acc[1][nt], a[1], b);
            }
        }
    };

    load_global(0);
    store_smem(0);
    __syncthreads();

    const int NKB = KDIM / BK;
    for (int kb = 0; kb < NKB; ++kb) {
        if (kb + 1 < NKB) load_global(kb + 1);
        compute(kb & 1);
        if (kb + 1 < NKB) store_smem((kb + 1) & 1);
        __syncthreads();
    }

    // ---------------- epilogue ----------------
    #pragma unroll
    for (int mt = 0; mt < 2; mt++) {
        #pragma unroll
        for (int half = 0; half < 2; half++) {
            int rloc = wm + mt * 16 + gq + half * 8;
            int grow = rowBase + rloc;
            if (grow >= rowEnd) continue;
            if (SECOND) {
                const int   tok = g_tok[grow];
                const float wgt = g_wt[grow];
                float* orow = Oglob + (size_t)tok * NDIM + nBase;
                #pragma unroll
                for (int nt = 0; nt < 8; nt++) {
                    int cc = wn + nt * 8 + tig * 2;
                    atomicAdd(&orow[cc],     acc[mt][nt][half * 2 + 0] * wgt);
                    atomicAdd(&orow[cc + 1], acc[mt][nt][half * 2 + 1] * wgt);
                }
            } else {
                float* hrow = g_h + (size_t)grow * NDIM + nBase;
                #pragma unroll
                for (int nt = 0; nt < 8; nt++) {
                    int cc = wn + nt * 8 + tig * 2;
                    float v0 = acc[mt][nt][half * 2 + 0];
                    float v1 = acc[mt][nt][half * 2 + 1];
                    hrow[cc]     = v0 / (1.f + __expf(-v0));   // silu
                    hrow[cc + 1] = v1 / (1.f + __expf(-v1));
                }
            }
        }
    }
}

// ---------------- launch ----------------
extern "C" void kernel_launch(void* const* d_in, const int* in_sizes, int n_in,
                              void* d_out, int out_size) {
    const float* x    = (const float*)d_in[0];
    const float* rw   = (const float*)d_in[1];
    const int*   se32 = (const int*)d_in[2];
    const float* w1   = (const float*)d_in[3];
    const float* w2   = (const float*)d_in[4];
    float*       out  = (float*)d_out;

    constexpr int SMEM_BYTES = (2 * 128 * 36 + 2 * 32 * 136) * 4;  // 71680

    cudaFuncSetAttribute((const void*)moe_gemm<DDIM, IDIM, false>,
                         cudaFuncAttributeMaxDynamicSharedMemorySize, SMEM_BYTES);
    cudaFuncSetAttribute((const void*)moe_gemm<IDIM, DDIM, true>,
                         cudaFuncAttributeMaxDynamicSharedMemorySize, SMEM_BYTES);

    int n4 = out_size / 4;
    zero_out_kernel<<<(n4 + 255) / 256, 256>>>((float4*)out, n4, se32);
    route_kernel<<<1, 256>>>(se32, rw);

    dim3 g1(IDIM / 128, NASN / 128, NEXP);   // (16, 64, 8)
    moe_gemm<DDIM, IDIM, false><<<g1, 256, SMEM_BYTES>>>(x, w1, out);

    dim3 g2(DDIM / 128, NASN / 128, NEXP);   // (8, 64, 8)
    moe_gemm<IDIM, DDIM, true><<<g2, 256, SMEM_BYTES>>>(g_h, w2, out);
}

// round 9
// speedup vs baseline: 1.4309x; 1.2407x over previous
#include <cuda_runtime.h>
#include <cuda_fp16.h>
#include <cstdint>

// Problem constants
#define NEXP   8
#define DDIM   1024
#define IDIM   2048
#define KTOP   2
#define NTOK   4096               // B*S
#define NASN   (NTOK * KTOP)      // 8192 assignments

// ---------------- device scratch (no allocations allowed) ----------------
__device__ int   g_is64;
__device__ int   g_count[NEXP];
__device__ int   g_offset[NEXP];
__device__ int   g_tok[NASN];
__device__ float g_wt[NASN];
__device__ float g_h[(size_t)NASN * IDIM];   // 64 MB intermediate activations (float, as R7)

// ---------------- helpers ----------------
__device__ __forceinline__ uint32_t h2_bits(__half2 h) {
    return *(uint32_t*)&h;
}

__device__ __forceinline__ void mma_f16_k8(float* c, const uint32_t* a, uint32_t b) {
    asm volatile(
        "mma.sync.aligned.m16n8k8.row.col.f32.f16.f16.f32 "
        "{%0,%1,%2,%3}, {%4,%5}, {%6}, {%0,%1,%2,%3};\n"
        : "+f"(c[0]), "+f"(c[1]), "+f"(c[2]), "+f"(c[3])
        : "r"(a[0]), "r"(a[1]), "r"(b));
}

// Fetch expert id for assignment i, handling int32 vs int64 wire format.
__device__ __forceinline__ int get_expert(const int* se32, int i) {
    int v = g_is64 ? se32[2 * i] : se32[i];   // little-endian low word for int64
    return v & (NEXP - 1);
}

// ---------------- dtype detection + zero ----------------
__global__ void zero_out_kernel(float4* out, int n4, const int* __restrict__ se32) {
    int i = blockIdx.x * blockDim.x + threadIdx.x;
    if (blockIdx.x == 0 && threadIdx.x == 0) {
        int nz = 0;
        #pragma unroll 8
        for (int j = 1; j < 256; j += 2) nz |= se32[j];
        g_is64 = (nz == 0) ? 1 : 0;
    }
    if (i < n4) out[i] = make_float4(0.f, 0.f, 0.f, 0.f);
}

// ---------------- routing: warp-per-expert ballot scan (deterministic, stable) ----------------
__global__ void route_kernel(const int* __restrict__ se32, const float* __restrict__ rw) {
    const int tid  = threadIdx.x;
    const int warp = tid >> 5;          // warp w owns expert w
    const int lane = tid & 31;
    const unsigned lt = (1u << lane) - 1u;

    int cnt = 0;
    for (int it = 0; it < NASN / 32; it++) {
        int i = it * 32 + lane;
        unsigned m = __ballot_sync(0xFFFFFFFFu, get_expert(se32, i) == warp);
        cnt += __popc(m);
    }
    if (lane == 0) g_count[warp] = cnt;
    __syncthreads();
    if (tid == 0) {
        int off = 0;
        for (int e = 0; e < NEXP; e++) { g_offset[e] = off; off += g_count[e]; }
    }
    __syncthreads();

    int base = g_offset[warp];
    for (int it = 0; it < NASN / 32; it++) {
        int i = it * 32 + lane;
        bool mine = (get_expert(se32, i) == warp);
        unsigned m = __ballot_sync(0xFFFFFFFFu, mine);
        if (mine) {
            int r = __popc(m & lt);
            g_tok[base + r] = i / KTOP;
            g_wt[base + r]  = rw[i];
        }
        base += __popc(m);
    }
}

// ---------------- grouped GEMM (fp16 mma.sync m16n8k8, 128x128x32, dbl-buffered) ----------------
// Structure identical to the R7-passing tf32 kernel; only smem dtype + frag loads + mma changed.
// SECOND == false : h = silu(X_gathered @ w1_e)  -> g_h (float)
// SECOND == true  : out[tok] += (g_h @ w2_e) * wt  (atomicAdd)
template <int KDIM, int NDIM, bool SECOND>
__global__ __launch_bounds__(256)
void moe_gemm(const float* __restrict__ Xin,
              const float* __restrict__ Wglob,
              float* __restrict__ Oglob) {
    constexpr int BM = 128, BN = 128, BK = 32;
    constexpr int ASTR = 40;    // halves per A row: frag word = 20*r + tig + k0/2 -> conflict-free
    constexpr int BSTR = 136;   // halves per B row: frag words 8*tig + n/2 -> bcast pairs, conflict-free

    extern __shared__ __half sh[];
    __half* As = sh;                       // [2][BM*ASTR]
    __half* Bs = sh + 2 * BM * ASTR;       // [2][BK*BSTR]

    const int e   = blockIdx.z;
    const int cnt = g_count[e];
    if ((int)blockIdx.y * BM >= cnt) return;

    const int off     = g_offset[e];
    const int rowBase = off + blockIdx.y * BM;   // global assignment row
    const int rowEnd  = off + cnt;
    const int nBase   = blockIdx.x * BN;
    const float* Wp   = Wglob + (size_t)e * KDIM * NDIM;

    const int tid  = threadIdx.x;
    const int lane = tid & 31;
    const int warp = tid >> 5;
    const int gq   = lane >> 2;          // groupID 0..7
    const int tig  = lane & 3;           // thread-in-group 0..3
    const int wm   = (warp >> 1) * 32;   // 4 warp-rows of 32
    const int wn   = (warp & 1) * 64;    // 2 warp-cols of 64

    // Per-thread A row pointers (gather for GEMM1, direct for GEMM2) — identical to R7
    const float* arow[4];
    int acol[4];
    #pragma unroll
    for (int j = 0; j < 4; j++) {
        int item = tid + j * 256;
        int r    = item >> 3;            // 0..127
        acol[j]  = (item & 7) * 4;
        int grow = rowBase + r;
        if (grow < rowEnd) {
            if (SECOND) arow[j] = g_h + (size_t)grow * KDIM;
            else        arow[j] = Xin + (size_t)g_tok[grow] * KDIM;
        } else {
            arow[j] = nullptr;
        }
    }

    float acc[2][8][4];
    #pragma unroll
    for (int mt = 0; mt < 2; mt++)
        #pragma unroll
        for (int nt = 0; nt < 8; nt++)
            #pragma unroll
            for (int q = 0; q < 4; q++) acc[mt][nt][q] = 0.f;

    float4 areg[4], breg[4];

    auto load_global = [&](int kb) {        // identical to R7
        #pragma unroll
        for (int j = 0; j < 4; j++) {
            if (arow[j]) areg[j] = *(const float4*)(arow[j] + kb * BK + acol[j]);
            else         areg[j] = make_float4(0.f, 0.f, 0.f, 0.f);
        }
        #pragma unroll
        for (int j = 0; j < 4; j++) {
            int item = tid + j * 256;
            int r = item >> 5;                 // k row 0..31
            int c = (item & 31) * 4;           // col 0..124
            breg[j] = *(const float4*)(Wp + (size_t)(kb * BK + r) * NDIM + nBase + c);
        }
    };

    auto store_smem = [&](int buf) {        // same indices as R7, f32 -> f16 convert
        __half* Ab = As + buf * BM * ASTR;
        __half* Bb = Bs + buf * BK * BSTR;
        #pragma unroll
        for (int j = 0; j < 4; j++) {
            int item = tid + j * 256;
            int r = item >> 3;
            int c = (item & 7) * 4;
            uint2 u;
            u.x = h2_bits(__floats2half2_rn(areg[j].x, areg[j].y));
            u.y = h2_bits(__floats2half2_rn(areg[j].z, areg[j].w));
            *(uint2*)(Ab + r * ASTR + c) = u;
        }
        #pragma unroll
        for (int j = 0; j < 4; j++) {
            int item = tid + j * 256;
            int r = item >> 5;
            int c = (item & 31) * 4;
            uint2 u;
            u.x = h2_bits(__floats2half2_rn(breg[j].x, breg[j].y));
            u.y = h2_bits(__floats2half2_rn(breg[j].z, breg[j].w));
            *(uint2*)(Bb + r * BSTR + c) = u;
        }
    };

    auto compute = [&](int buf) {
        const __half* Ab = As + buf * BM * ASTR;
        const unsigned short* Bu = (const unsigned short*)(Bs + buf * BK * BSTR);
        #pragma unroll
        for (int ks = 0; ks < 4; ks++) {
            const int k0 = ks * 8;
            uint32_t a[2][2];
            #pragma unroll
            for (int mt = 0; mt < 2; mt++) {
                int r = wm + mt * 16 + gq;
                a[mt][0] = *(const uint32_t*)(Ab + r * ASTR + k0 + 2 * tig);
                a[mt][1] = *(const uint32_t*)(Ab + (r + 8) * ASTR + k0 + 2 * tig);
            }
            #pragma unroll
            for (int nt = 0; nt < 8; nt++) {
                int n = wn + nt * 8 + gq;
                uint32_t l0 = Bu[(k0 + 2 * tig)     * BSTR + n];
                uint32_t l1 = Bu[(k0 + 2 * tig + 1) * BSTR + n];
                uint32_t b = l0 | (l1 << 16);
                mma_f16_k8(acc[0][nt], a[0], b);
                mma_f16_k8(acc[1][nt], a[1], b);
            }
        }
    };

    load_global(0);
    store_smem(0);
    __syncthreads();

    const int NKB = KDIM / BK;
    for (int kb = 0; kb < NKB; ++kb) {
        if (kb + 1 < NKB) load_global(kb + 1);
        compute(kb & 1);
        if (kb + 1 < NKB) store_smem((kb + 1) & 1);
        __syncthreads();
    }

    // ---------------- epilogue (identical to R7) ----------------
    #pragma unroll
    for (int mt = 0; mt < 2; mt++) {
        #pragma unroll
        for (int half = 0; half < 2; half++) {
            int rloc = wm + mt * 16 + gq + half * 8;
            int grow = rowBase + rloc;
            if (grow >= rowEnd) continue;
            if (SECOND) {
                const int   tok = g_tok[grow];
                const float wgt = g_wt[grow];
                float* orow = Oglob + (size_t)tok * NDIM + nBase;
                #pragma unroll
                for (int nt = 0; nt < 8; nt++) {
                    int cc = wn + nt * 8 + tig * 2;
                    atomicAdd(&orow[cc],     acc[mt][nt][half * 2 + 0] * wgt);
                    atomicAdd(&orow[cc + 1], acc[mt][nt][half * 2 + 1] * wgt);
                }
            } else {
                float* hrow = g_h + (size_t)grow * NDIM + nBase;
                #pragma unroll
                for (int nt = 0; nt < 8; nt++) {
                    int cc = wn + nt * 8 + tig * 2;
                    float v0 = acc[mt][nt][half * 2 + 0];
                    float v1 = acc[mt][nt][half * 2 + 1];
                    hrow[cc]     = v0 / (1.f + __expf(-v0));   // silu
                    hrow[cc + 1] = v1 / (1.f + __expf(-v1));
                }
            }
        }
    }
}

// ---------------- launch ----------------
extern "C" void kernel_launch(void* const* d_in, const int* in_sizes, int n_in,
                              void* d_out, int out_size) {
    const float* x    = (const float*)d_in[0];
    const float* rw   = (const float*)d_in[1];
    const int*   se32 = (const int*)d_in[2];
    const float* w1   = (const float*)d_in[3];
    const float* w2   = (const float*)d_in[4];
    float*       out  = (float*)d_out;

    constexpr int SMEM_BYTES = (2 * 128 * 40 + 2 * 32 * 136) * 2;  // 37888

    cudaFuncSetAttribute((const void*)moe_gemm<DDIM, IDIM, false>,
                         cudaFuncAttributeMaxDynamicSharedMemorySize, SMEM_BYTES);
    cudaFuncSetAttribute((const void*)moe_gemm<IDIM, DDIM, true>,
                         cudaFuncAttributeMaxDynamicSharedMemorySize, SMEM_BYTES);

    int n4 = out_size / 4;
    zero_out_kernel<<<(n4 + 255) / 256, 256>>>((float4*)out, n4, se32);
    route_kernel<<<1, 256>>>(se32, rw);

    dim3 g1(IDIM / 128, NASN / 128, NEXP);   // (16, 64, 8)
    moe_gemm<DDIM, IDIM, false><<<g1, 256, SMEM_BYTES>>>(x, w1, out);

    dim3 g2(DDIM / 128, NASN / 128, NEXP);   // (8, 64, 8)
    moe_gemm<IDIM, DDIM, true><<<g2, 256, SMEM_BYTES>>>(g_h, w2, out);
}

// round 10
// speedup vs baseline: 1.6995x; 1.1878x over previous
#include <cuda_runtime.h>
#include <cuda_fp16.h>
#include <cstdint>

// Problem constants
#define NEXP   8
#define DDIM   1024
#define IDIM   2048
#define KTOP   2
#define NTOK   4096               // B*S
#define NASN   (NTOK * KTOP)      // 8192 assignments

// ---------------- device scratch (no allocations allowed) ----------------
__device__ int   g_is64;
__device__ int   g_count[NEXP];
__device__ int   g_offset[NEXP];
__device__ int   g_tok[NASN];
__device__ float g_wt[NASN];
__device__ float g_h[(size_t)NASN * IDIM];   // 64 MB intermediate activations

// ---------------- helpers ----------------
__device__ __forceinline__ uint32_t h2_bits(__half2 h) {
    return *(uint32_t*)&h;
}

__device__ __forceinline__ uint32_t smem_u32(const void* p) {
    uint32_t a;
    asm("{ .reg .u64 t; cvta.to.shared.u64 t, %1; cvt.u32.u64 %0, t; }" : "=r"(a) : "l"(p));
    return a;
}

__device__ __forceinline__ void ldsm_x4(uint32_t& r0, uint32_t& r1, uint32_t& r2, uint32_t& r3,
                                        uint32_t addr) {
    asm volatile("ldmatrix.sync.aligned.m8n8.x4.shared.b16 {%0,%1,%2,%3}, [%4];"
                 : "=r"(r0), "=r"(r1), "=r"(r2), "=r"(r3) : "r"(addr));
}

__device__ __forceinline__ void ldsm_x4_t(uint32_t& r0, uint32_t& r1, uint32_t& r2, uint32_t& r3,
                                          uint32_t addr) {
    asm volatile("ldmatrix.sync.aligned.m8n8.x4.trans.shared.b16 {%0,%1,%2,%3}, [%4];"
                 : "=r"(r0), "=r"(r1), "=r"(r2), "=r"(r3) : "r"(addr));
}

__device__ __forceinline__ void mma_f16_k16(float* c, const uint32_t* a, uint32_t b0, uint32_t b1) {
    asm volatile(
        "mma.sync.aligned.m16n8k16.row.col.f32.f16.f16.f32 "
        "{%0,%1,%2,%3}, {%4,%5,%6,%7}, {%8,%9}, {%0,%1,%2,%3};\n"
        : "+f"(c[0]), "+f"(c[1]), "+f"(c[2]), "+f"(c[3])
        : "r"(a[0]), "r"(a[1]), "r"(a[2]), "r"(a[3]), "r"(b0), "r"(b1));
}

// Fetch expert id for assignment i, handling int32 vs int64 wire format.
__device__ __forceinline__ int get_expert(const int* se32, int i) {
    int v = g_is64 ? se32[2 * i] : se32[i];   // little-endian low word for int64
    return v & (NEXP - 1);
}

// ---------------- dtype detection + zero ----------------
__global__ void zero_out_kernel(float4* out, int n4, const int* __restrict__ se32) {
    int i = blockIdx.x * blockDim.x + threadIdx.x;
    if (blockIdx.x == 0 && threadIdx.x == 0) {
        int nz = 0;
        #pragma unroll 8
        for (int j = 1; j < 256; j += 2) nz |= se32[j];
        g_is64 = (nz == 0) ? 1 : 0;
    }
    if (i < n4) out[i] = make_float4(0.f, 0.f, 0.f, 0.f);
}

// ---------------- routing: warp-per-expert ballot scan (deterministic, stable) ----------------
__global__ void route_kernel(const int* __restrict__ se32, const float* __restrict__ rw) {
    const int tid  = threadIdx.x;
    const int warp = tid >> 5;          // warp w owns expert w
    const int lane = tid & 31;
    const unsigned lt = (1u << lane) - 1u;

    int cnt = 0;
    for (int it = 0; it < NASN / 32; it++) {
        int i = it * 32 + lane;
        unsigned m = __ballot_sync(0xFFFFFFFFu, get_expert(se32, i) == warp);
        cnt += __popc(m);
    }
    if (lane == 0) g_count[warp] = cnt;
    __syncthreads();
    if (tid == 0) {
        int off = 0;
        for (int e = 0; e < NEXP; e++) { g_offset[e] = off; off += g_count[e]; }
    }
    __syncthreads();

    int base = g_offset[warp];
    for (int it = 0; it < NASN / 32; it++) {
        int i = it * 32 + lane;
        bool mine = (get_expert(se32, i) == warp);
        unsigned m = __ballot_sync(0xFFFFFFFFu, mine);
        if (mine) {
            int r = __popc(m & lt);
            g_tok[base + r] = i / KTOP;
            g_wt[base + r]  = rw[i];
        }
        base += __popc(m);
    }
}

// ---------------- grouped GEMM (fp16 mma m16n8k16 + ldmatrix, 128x128x32, dbl-buffered) ----------------
// Identical to the R9-passing kernel except the compute loop (ldmatrix + k16 mma).
// SECOND == false : h = silu(X_gathered @ w1_e)  -> g_h (float)
// SECOND == true  : out[tok] += (g_h @ w2_e) * wt  (atomicAdd)
template <int KDIM, int NDIM, bool SECOND>
__global__ __launch_bounds__(256)
void moe_gemm(const float* __restrict__ Xin,
              const float* __restrict__ Wglob,
              float* __restrict__ Oglob) {
    constexpr int BM = 128, BN = 128, BK = 32;
    constexpr int ASTR = 40;    // halves per A row: 80B stride -> LDSM rows hit distinct 16B slots
    constexpr int BSTR = 136;   // halves per B row: 272B stride -> LDSM rows hit distinct 16B slots

    extern __shared__ __half sh[];
    __half* As = sh;                       // [2][BM*ASTR]
    __half* Bs = sh + 2 * BM * ASTR;       // [2][BK*BSTR]

    const int e   = blockIdx.z;
    const int cnt = g_count[e];
    if ((int)blockIdx.y * BM >= cnt) return;

    const int off     = g_offset[e];
    const int rowBase = off + blockIdx.y * BM;   // global assignment row
    const int rowEnd  = off + cnt;
    const int nBase   = blockIdx.x * BN;
    const float* Wp   = Wglob + (size_t)e * KDIM * NDIM;

    const int tid  = threadIdx.x;
    const int lane = tid & 31;
    const int warp = tid >> 5;
    const int gq   = lane >> 2;          // groupID 0..7
    const int tig  = lane & 3;           // thread-in-group 0..3
    const int wm   = (warp >> 1) * 32;   // 4 warp-rows of 32
    const int wn   = (warp & 1) * 64;    // 2 warp-cols of 64

    // ldmatrix per-lane addressing: group g = lane>>3 (matrices 0..3), lr = lane&7
    const int lg = lane >> 3;
    const int lr = lane & 7;
    const int mrow_off = ((lg & 1) ? 8 : 0) + lr;   // +8 rows for matrices 1,3
    const int kcol_off = (lg >= 2) ? 8 : 0;         // +8 k for matrices 2,3

    // Per-thread A row pointers (gather for GEMM1, direct for GEMM2) — identical to R9
    const float* arow[4];
    int acol[4];
    #pragma unroll
    for (int j = 0; j < 4; j++) {
        int item = tid + j * 256;
        int r    = item >> 3;            // 0..127
        acol[j]  = (item & 7) * 4;
        int grow = rowBase + r;
        if (grow < rowEnd) {
            if (SECOND) arow[j] = g_h + (size_t)grow * KDIM;
            else        arow[j] = Xin + (size_t)g_tok[grow] * KDIM;
        } else {
            arow[j] = nullptr;
        }
    }

    float acc[2][8][4];
    #pragma unroll
    for (int mt = 0; mt < 2; mt++)
        #pragma unroll
        for (int nt = 0; nt < 8; nt++)
            #pragma unroll
            for (int q = 0; q < 4; q++) acc[mt][nt][q] = 0.f;

    float4 areg[4], breg[4];

    auto load_global = [&](int kb) {        // identical to R9
        #pragma unroll
        for (int j = 0; j < 4; j++) {
            if (arow[j]) areg[j] = *(const float4*)(arow[j] + kb * BK + acol[j]);
            else         areg[j] = make_float4(0.f, 0.f, 0.f, 0.f);
        }
        #pragma unroll
        for (int j = 0; j < 4; j++) {
            int item = tid + j * 256;
            int r = item >> 5;                 // k row 0..31
            int c = (item & 31) * 4;           // col 0..124
            breg[j] = *(const float4*)(Wp + (size_t)(kb * BK + r) * NDIM + nBase + c);
        }
    };

    auto store_smem = [&](int buf) {        // identical to R9
        __half* Ab = As + buf * BM * ASTR;
        __half* Bb = Bs + buf * BK * BSTR;
        #pragma unroll
        for (int j = 0; j < 4; j++) {
            int item = tid + j * 256;
            int r = item >> 3;
            int c = (item & 7) * 4;
            uint2 u;
            u.x = h2_bits(__floats2half2_rn(areg[j].x, areg[j].y));
            u.y = h2_bits(__floats2half2_rn(areg[j].z, areg[j].w));
            *(uint2*)(Ab + r * ASTR + c) = u;
        }
        #pragma unroll
        for (int j = 0; j < 4; j++) {
            int item = tid + j * 256;
            int r = item >> 5;
            int c = (item & 31) * 4;
            uint2 u;
            u.x = h2_bits(__floats2half2_rn(breg[j].x, breg[j].y));
            u.y = h2_bits(__floats2half2_rn(breg[j].z, breg[j].w));
            *(uint2*)(Bb + r * BSTR + c) = u;
        }
    };

    auto compute = [&](int buf) {
        const uint32_t abase = smem_u32(As + buf * BM * ASTR);
        const uint32_t bbase = smem_u32(Bs + buf * BK * BSTR);
        #pragma unroll
        for (int ks = 0; ks < 2; ks++) {
            const int k0 = ks * 16;
            // A fragments: one ldmatrix.x4 per 16-row tile
            uint32_t a[2][4];
            #pragma unroll
            for (int mt = 0; mt < 2; mt++) {
                uint32_t addr = abase +
                    (uint32_t)((wm + mt * 16 + mrow_off) * ASTR + k0 + kcol_off) * 2u;
                ldsm_x4(a[mt][0], a[mt][1], a[mt][2], a[mt][3], addr);
            }
            // B fragments: one ldmatrix.x4.trans per 16-col n-group (covers nt=2*nt2, 2*nt2+1)
            uint32_t b[4][4];
            #pragma unroll
            for (int nt2 = 0; nt2 < 4; nt2++) {
                uint32_t addr = bbase +
                    (uint32_t)((k0 + mrow_off) * BSTR + wn + nt2 * 16 + kcol_off) * 2u;
                ldsm_x4_t(b[nt2][0], b[nt2][1], b[nt2][2], b[nt2][3], addr);
            }
            #pragma unroll
            for (int nt2 = 0; nt2 < 4; nt2++) {
                mma_f16_k16(acc[0][2 * nt2],     a[0], b[nt2][0], b[nt2][1]);
                mma_f16_k16(acc[1][2 * nt2],     a[1], b[nt2][0], b[nt2][1]);
                mma_f16_k16(acc[0][2 * nt2 + 1], a[0], b[nt2][2], b[nt2][3]);
                mma_f16_k16(acc[1][2 * nt2 + 1], a[1], b[nt2][2], b[nt2][3]);
            }
        }
    };

    load_global(0);
    store_smem(0);
    __syncthreads();

    const int NKB = KDIM / BK;
    for (int kb = 0; kb < NKB; ++kb) {
        if (kb + 1 < NKB) load_global(kb + 1);
        compute(kb & 1);
        if (kb + 1 < NKB) store_smem((kb + 1) & 1);
        __syncthreads();
    }

    // ---------------- epilogue (identical to R9) ----------------
    #pragma unroll
    for (int mt = 0; mt < 2; mt++) {
        #pragma unroll
        for (int half = 0; half < 2; half++) {
            int rloc = wm + mt * 16 + gq + half * 8;
            int grow = rowBase + rloc;
            if (grow >= rowEnd) continue;
            if (SECOND) {
                const int   tok = g_tok[grow];
                const float wgt = g_wt[grow];
                float* orow = Oglob + (size_t)tok * NDIM + nBase;
                #pragma unroll
                for (int nt = 0; nt < 8; nt++) {
                    int cc = wn + nt * 8 + tig * 2;
                    atomicAdd(&orow[cc],     acc[mt][nt][half * 2 + 0] * wgt);
                    atomicAdd(&orow[cc + 1], acc[mt][nt][half * 2 + 1] * wgt);
                }
            } else {
                float* hrow = g_h + (size_t)grow * NDIM + nBase;
                #pragma unroll
                for (int nt = 0; nt < 8; nt++) {
                    int cc = wn + nt * 8 + tig * 2;
                    float v0 = acc[mt][nt][half * 2 + 0];
                    float v1 = acc[mt][nt][half * 2 + 1];
                    hrow[cc]     = v0 / (1.f + __expf(-v0));   // silu
                    hrow[cc + 1] = v1 / (1.f + __expf(-v1));
                }
            }
        }
    }
}

// ---------------- launch ----------------
extern "C" void kernel_launch(void* const* d_in, const int* in_sizes, int n_in,
                              void* d_out, int out_size) {
    const float* x    = (const float*)d_in[0];
    const float* rw   = (const float*)d_in[1];
    const int*   se32 = (const int*)d_in[2];
    const float* w1   = (const float*)d_in[3];
    const float* w2   = (const float*)d_in[4];
    float*       out  = (float*)d_out;

    constexpr int SMEM_BYTES = (2 * 128 * 40 + 2 * 32 * 136) * 2;  // 37888

    cudaFuncSetAttribute((const void*)moe_gemm<DDIM, IDIM, false>,
                         cudaFuncAttributeMaxDynamicSharedMemorySize, SMEM_BYTES);
    cudaFuncSetAttribute((const void*)moe_gemm<IDIM, DDIM, true>,
                         cudaFuncAttributeMaxDynamicSharedMemorySize, SMEM_BYTES);

    int n4 = out_size / 4;
    zero_out_kernel<<<(n4 + 255) / 256, 256>>>((float4*)out, n4, se32);
    route_kernel<<<1, 256>>>(se32, rw);

    dim3 g1(IDIM / 128, NASN / 128, NEXP);   // (16, 64, 8)
    moe_gemm<DDIM, IDIM, false><<<g1, 256, SMEM_BYTES>>>(x, w1, out);

    dim3 g2(DDIM / 128, NASN / 128, NEXP);   // (8, 64, 8)
    moe_gemm<IDIM, DDIM, true><<<g2, 256, SMEM_BYTES>>>(g_h, w2, out);
}

// round 12
// speedup vs baseline: 2.2328x; 1.3138x over previous
#include <cuda_runtime.h>
#include <cuda_fp16.h>
#include <cstdint>

// Problem constants
#define NEXP   8
#define DDIM   1024
#define IDIM   2048
#define KTOP   2
#define NTOK   4096               // B*S
#define NASN   (NTOK * KTOP)      // 8192 assignments

// ---------------- device scratch (no allocations allowed) ----------------
__device__ int    g_is64;
__device__ int    g_count[NEXP];
__device__ int    g_offset[NEXP];
__device__ int    g_tok[NASN];
__device__ float  g_wt[NASN];
__device__ __half g_xh[(size_t)NTOK * DDIM];            // 8 MB  x (fp16)
__device__ __half g_h[(size_t)NASN * IDIM];             // 32 MB silu(h) (fp16)
__device__ __half g_w1h[(size_t)NEXP * DDIM * IDIM];    // 32 MB w1 (fp16)
__device__ __half g_w2h[(size_t)NEXP * DDIM * IDIM];    // 32 MB w2 (fp16)

// ---------------- helpers ----------------
__device__ __forceinline__ uint32_t h2_bits(__half2 h) {
    return *(uint32_t*)&h;
}

__device__ __forceinline__ uint32_t smem_u32(const void* p) {
    uint32_t a;
    asm("{ .reg .u64 t; cvta.to.shared.u64 t, %1; cvt.u32.u64 %0, t; }" : "=r"(a) : "l"(p));
    return a;
}

__device__ __forceinline__ void ldsm_x4(uint32_t& r0, uint32_t& r1, uint32_t& r2, uint32_t& r3,
                                        uint32_t addr) {
    asm volatile("ldmatrix.sync.aligned.m8n8.x4.shared.b16 {%0,%1,%2,%3}, [%4];"
                 : "=r"(r0), "=r"(r1), "=r"(r2), "=r"(r3) : "r"(addr));
}

__device__ __forceinline__ void ldsm_x4_t(uint32_t& r0, uint32_t& r1, uint32_t& r2, uint32_t& r3,
                                          uint32_t addr) {
    asm volatile("ldmatrix.sync.aligned.m8n8.x4.trans.shared.b16 {%0,%1,%2,%3}, [%4];"
                 : "=r"(r0), "=r"(r1), "=r"(r2), "=r"(r3) : "r"(addr));
}

__device__ __forceinline__ void mma_f16_k16(float* c, const uint32_t* a, uint32_t b0, uint32_t b1) {
    asm volatile(
        "mma.sync.aligned.m16n8k16.row.col.f32.f16.f16.f32 "
        "{%0,%1,%2,%3}, {%4,%5,%6,%7}, {%8,%9}, {%0,%1,%2,%3};\n"
        : "+f"(c[0]), "+f"(c[1]), "+f"(c[2]), "+f"(c[3])
        : "r"(a[0]), "r"(a[1]), "r"(a[2]), "r"(a[3]), "r"(b0), "r"(b1));
}

// Fetch expert id for assignment i, handling int32 vs int64 wire format.
__device__ __forceinline__ int get_expert(const int* se32, int i) {
    int v = g_is64 ? se32[2 * i] : se32[i];   // little-endian low word for int64
    return v & (NEXP - 1);
}

// ---------------- dtype detection + zero ----------------
__global__ void zero_out_kernel(float4* out, int n4, const int* __restrict__ se32) {
    int i = blockIdx.x * blockDim.x + threadIdx.x;
    if (blockIdx.x == 0 && threadIdx.x == 0) {
        int nz = 0;
        #pragma unroll 8
        for (int j = 1; j < 256; j += 2) nz |= se32[j];
        g_is64 = (nz == 0) ? 1 : 0;
    }
    if (i < n4) out[i] = make_float4(0.f, 0.f, 0.f, 0.f);
}

// ---------------- f32 -> f16 conversion pass (dst resolved via cudaGetSymbolAddress) ----------------
__global__ void conv_half_kernel(const float4* __restrict__ in, uint2* __restrict__ outp, int n4) {
    int i = blockIdx.x * blockDim.x + threadIdx.x;
    if (i < n4) {
        float4 v = in[i];
        uint2 u;
        u.x = h2_bits(__floats2half2_rn(v.x, v.y));
        u.y = h2_bits(__floats2half2_rn(v.z, v.w));
        outp[i] = u;
    }
}

// ---------------- routing: warp-per-expert ballot scan (deterministic, stable) ----------------
__global__ void route_kernel(const int* __restrict__ se32, const float* __restrict__ rw) {
    const int tid  = threadIdx.x;
    const int warp = tid >> 5;          // warp w owns expert w
    const int lane = tid & 31;
    const unsigned lt = (1u << lane) - 1u;

    int cnt = 0;
    for (int it = 0; it < NASN / 32; it++) {
        int i = it * 32 + lane;
        unsigned m = __ballot_sync(0xFFFFFFFFu, get_expert(se32, i) == warp);
        cnt += __popc(m);
    }
    if (lane == 0) g_count[warp] = cnt;
    __syncthreads();
    if (tid == 0) {
        int off = 0;
        for (int e = 0; e < NEXP; e++) { g_offset[e] = off; off += g_count[e]; }
    }
    __syncthreads();

    int base = g_offset[warp];
    for (int it = 0; it < NASN / 32; it++) {
        int i = it * 32 + lane;
        bool mine = (get_expert(se32, i) == warp);
        unsigned m = __ballot_sync(0xFFFFFFFFu, mine);
        if (mine) {
            int r = __popc(m & lt);
            g_tok[base + r] = i / KTOP;
            g_wt[base + r]  = rw[i];
        }
        base += __popc(m);
    }
}

// ---------------- grouped GEMM (fp16 mma m16n8k16 + ldmatrix, 128x128x32, dbl-buffered) ----------------
// All operands fp16 in GMEM; A/W/output-h referenced via DEVICE GLOBALS (SECOND flag),
// never via host-passed __device__ symbol addresses.
// SECOND == false : g_h = half(silu(gather(g_xh) @ g_w1h))
// SECOND == true  : out[tok] += (g_h @ g_w2h) * wt  (atomicAdd)
template <int KDIM, int NDIM, bool SECOND>
__global__ __launch_bounds__(256)
void moe_gemm(float* __restrict__ Oglob) {
    constexpr int BM = 128, BN = 128, BK = 32;
    constexpr int ASTR = 40;    // halves per A row: 80B stride -> LDSM rows hit distinct 16B slots
    constexpr int BSTR = 136;   // halves per B row: 272B stride -> LDSM rows hit distinct 16B slots

    extern __shared__ __half sh[];
    __half* As = sh;                       // [2][BM*ASTR]
    __half* Bs = sh + 2 * BM * ASTR;       // [2][BK*BSTR]

    const __half* Ain  = SECOND ? g_h : g_xh;
    const __half* Wall = SECOND ? g_w2h : g_w1h;

    const int e   = blockIdx.z;
    const int cnt = g_count[e];
    if ((int)blockIdx.y * BM >= cnt) return;

    const int off     = g_offset[e];
    const int rowBase = off + blockIdx.y * BM;   // global assignment row
    const int rowEnd  = off + cnt;
    const int nBase   = blockIdx.x * BN;
    const __half* Wp  = Wall + (size_t)e * KDIM * NDIM;

    const int tid  = threadIdx.x;
    const int lane = tid & 31;
    const int warp = tid >> 5;
    const int gq   = lane >> 2;          // groupID 0..7
    const int tig  = lane & 3;           // thread-in-group 0..3
    const int wm   = (warp >> 1) * 32;   // 4 warp-rows of 32
    const int wn   = (warp & 1) * 64;    // 2 warp-cols of 64

    // ldmatrix per-lane addressing
    const int lg = lane >> 3;
    const int lr = lane & 7;
    const int mrow_off = ((lg & 1) ? 8 : 0) + lr;
    const int kcol_off = (lg >= 2) ? 8 : 0;

    // ---- copy plans (uint4 = 8 halves) ----
    // A: 512 uint4/stage: r = chunk>>2 (0..127), c8 = (chunk&3)*8
    const __half* asrc[2]; uint32_t adst[2];
    #pragma unroll
    for (int j = 0; j < 2; j++) {
        int chunk = tid + j * 256;
        int r = chunk >> 2, c8 = (chunk & 3) * 8;
        adst[j] = (uint32_t)(r * ASTR + c8);
        int grow = rowBase + r;
        if (grow < rowEnd) {
            asrc[j] = Ain + (size_t)(SECOND ? grow : g_tok[grow]) * KDIM + c8;
        } else {
            asrc[j] = nullptr;
        }
    }
    // B: 512 uint4/stage: k = chunk>>4 (0..31), c8 = (chunk&15)*8
    const __half* bsrc[2]; uint32_t bdst[2];
    #pragma unroll
    for (int j = 0; j < 2; j++) {
        int chunk = tid + j * 256;
        int k = chunk >> 4, c8 = (chunk & 15) * 8;
        bdst[j] = (uint32_t)(k * BSTR + c8);
        bsrc[j] = Wp + (size_t)k * NDIM + nBase + c8;
    }

    float acc[2][8][4];
    #pragma unroll
    for (int mt = 0; mt < 2; mt++)
        #pragma unroll
        for (int nt = 0; nt < 8; nt++)
            #pragma unroll
            for (int q = 0; q < 4; q++) acc[mt][nt][q] = 0.f;

    uint4 aS[2], bS[2];

    auto load_global = [&](int kb) {
        #pragma unroll
        for (int j = 0; j < 2; j++) {
            if (asrc[j]) aS[j] = *(const uint4*)(asrc[j] + kb * BK);
            else         aS[j] = make_uint4(0u, 0u, 0u, 0u);
        }
        #pragma unroll
        for (int j = 0; j < 2; j++)
            bS[j] = *(const uint4*)(bsrc[j] + (size_t)kb * BK * NDIM);
    };

    auto store_smem = [&](int buf) {
        __half* Ab = As + buf * BM * ASTR;
        __half* Bb = Bs + buf * BK * BSTR;
        #pragma unroll
        for (int j = 0; j < 2; j++) *(uint4*)(Ab + adst[j]) = aS[j];
        #pragma unroll
        for (int j = 0; j < 2; j++) *(uint4*)(Bb + bdst[j]) = bS[j];
    };

    auto compute = [&](int buf) {
        const uint32_t abase = smem_u32(As + buf * BM * ASTR);
        const uint32_t bbase = smem_u32(Bs + buf * BK * BSTR);
        #pragma unroll
        for (int ks = 0; ks < 2; ks++) {
            const int k0 = ks * 16;
            uint32_t a[2][4];
            #pragma unroll
            for (int mt = 0; mt < 2; mt++) {
                uint32_t addr = abase +
                    (uint32_t)((wm + mt * 16 + mrow_off) * ASTR + k0 + kcol_off) * 2u;
                ldsm_x4(a[mt][0], a[mt][1], a[mt][2], a[mt][3], addr);
            }
            uint32_t b[4][4];
            #pragma unroll
            for (int nt2 = 0; nt2 < 4; nt2++) {
                uint32_t addr = bbase +
                    (uint32_t)((k0 + mrow_off) * BSTR + wn + nt2 * 16 + kcol_off) * 2u;
                ldsm_x4_t(b[nt2][0], b[nt2][1], b[nt2][2], b[nt2][3], addr);
            }
            #pragma unroll
            for (int nt2 = 0; nt2 < 4; nt2++) {
                mma_f16_k16(acc[0][2 * nt2],     a[0], b[nt2][0], b[nt2][1]);
                mma_f16_k16(acc[1][2 * nt2],     a[1], b[nt2][0], b[nt2][1]);
                mma_f16_k16(acc[0][2 * nt2 + 1], a[0], b[nt2][2], b[nt2][3]);
                mma_f16_k16(acc[1][2 * nt2 + 1], a[1], b[nt2][2], b[nt2][3]);
            }
        }
    };

    load_global(0);
    store_smem(0);
    __syncthreads();

    const int NKB = KDIM / BK;
    for (int kb = 0; kb < NKB; ++kb) {
        if (kb + 1 < NKB) load_global(kb + 1);
        compute(kb & 1);
        if (kb + 1 < NKB) store_smem((kb + 1) & 1);
        __syncthreads();
    }

    // ---------------- epilogue ----------------
    #pragma unroll
    for (int mt = 0; mt < 2; mt++) {
        #pragma unroll
        for (int half = 0; half < 2; half++) {
            int rloc = wm + mt * 16 + gq + half * 8;
            int grow = rowBase + rloc;
            if (grow >= rowEnd) continue;
            if (SECOND) {
                const int   tok = g_tok[grow];
                const float wgt = g_wt[grow];
                float* orow = Oglob + (size_t)tok * NDIM + nBase;
                #pragma unroll
                for (int nt = 0; nt < 8; nt++) {
                    int cc = wn + nt * 8 + tig * 2;
                    atomicAdd(&orow[cc],     acc[mt][nt][half * 2 + 0] * wgt);
                    atomicAdd(&orow[cc + 1], acc[mt][nt][half * 2 + 1] * wgt);
                }
            } else {
                __half* hrow = g_h + (size_t)grow * NDIM + nBase;
                #pragma unroll
                for (int nt = 0; nt < 8; nt++) {
                    int cc = wn + nt * 8 + tig * 2;
                    float v0 = acc[mt][nt][half * 2 + 0];
                    float v1 = acc[mt][nt][half * 2 + 1];
                    float s0 = v0 / (1.f + __expf(-v0));   // silu
                    float s1 = v1 / (1.f + __expf(-v1));
                    *(__half2*)(hrow + cc) = __floats2half2_rn(s0, s1);
                }
            }
        }
    }
}

// ---------------- launch ----------------
extern "C" void kernel_launch(void* const* d_in, const int* in_sizes, int n_in,
                              void* d_out, int out_size) {
    const float* x    = (const float*)d_in[0];
    const float* rw   = (const float*)d_in[1];
    const int*   se32 = (const int*)d_in[2];
    const float* w1   = (const float*)d_in[3];
    const float* w2   = (const float*)d_in[4];
    float*       out  = (float*)d_out;

    constexpr int SMEM_BYTES = (2 * 128 * 40 + 2 * 32 * 136) * 2;  // 37888

    // Resolve device-scratch addresses properly (host code must NOT use
    // __device__ symbols as pointers directly).
    static void* p_xh  = nullptr;
    static void* p_w1h = nullptr;
    static void* p_w2h = nullptr;
    if (!p_xh) {
        cudaGetSymbolAddress(&p_xh,  g_xh);
        cudaGetSymbolAddress(&p_w1h, g_w1h);
        cudaGetSymbolAddress(&p_w2h, g_w2h);
        cudaFuncSetAttribute((const void*)moe_gemm<DDIM, IDIM, false>,
                             cudaFuncAttributeMaxDynamicSharedMemorySize, SMEM_BYTES);
        cudaFuncSetAttribute((const void*)moe_gemm<IDIM, DDIM, true>,
                             cudaFuncAttributeMaxDynamicSharedMemorySize, SMEM_BYTES);
    }

    int n4 = out_size / 4;                 // 1M float4 (out and x same size)
    int w4 = (NEXP * DDIM * IDIM) / 4;     // 4M float4 per weight tensor

    // 1: zero + dtype detect, 2: route, 3-5: fp16 conversions
    zero_out_kernel<<<(n4 + 255) / 256, 256>>>((float4*)out, n4, se32);
    route_kernel<<<1, 256>>>(se32, rw);
    conv_half_kernel<<<(n4 + 255) / 256, 256>>>((const float4*)x, (uint2*)p_xh, n4);
    conv_half_kernel<<<(w4 + 255) / 256, 256>>>((const float4*)w1, (uint2*)p_w1h, w4);
    conv_half_kernel<<<(w4 + 255) / 256, 256>>>((const float4*)w2, (uint2*)p_w2h, w4);

    // 6: GEMM1 (ncu -s 5 -c 1 captures this)
    dim3 g1(IDIM / 128, NASN / 128, NEXP);   // (16, 64, 8)
    moe_gemm<DDIM, IDIM, false><<<g1, 256, SMEM_BYTES>>>(out);

    // 7: GEMM2
    dim3 g2(DDIM / 128, NASN / 128, NEXP);   // (8, 64, 8)
    moe_gemm<IDIM, DDIM, true><<<g2, 256, SMEM_BYTES>>>(out);
}

// round 13
// speedup vs baseline: 2.2595x; 1.0120x over previous
#include <cuda_runtime.h>
#include <cuda_fp16.h>
#include <cstdint>

// Problem constants
#define NEXP   8
#define DDIM   1024
#define IDIM   2048
#define KTOP   2
#define NTOK   4096               // B*S
#define NASN   (NTOK * KTOP)      // 8192 assignments

// ---------------- device scratch (no allocations allowed) ----------------
__device__ int    g_is64;
__device__ int    g_count[NEXP];
__device__ int    g_offset[NEXP];
__device__ int    g_tok[NASN];
__device__ float  g_wt[NASN];
__device__ __half g_xh[(size_t)NTOK * DDIM];            // 8 MB  x (fp16)
__device__ __half g_h[(size_t)NASN * IDIM];             // 32 MB silu(h) (fp16)
__device__ __half g_w1h[(size_t)NEXP * DDIM * IDIM];    // 32 MB w1 (fp16)
__device__ __half g_w2h[(size_t)NEXP * DDIM * IDIM];    // 32 MB w2 (fp16)

// ---------------- helpers ----------------
__device__ __forceinline__ uint32_t h2_bits(__half2 h) {
    return *(uint32_t*)&h;
}

__device__ __forceinline__ uint32_t smem_u32(const void* p) {
    uint32_t a;
    asm("{ .reg .u64 t; cvta.to.shared.u64 t, %1; cvt.u32.u64 %0, t; }" : "=r"(a) : "l"(p));
    return a;
}

__device__ __forceinline__ void cp_async16(uint32_t dst, const void* src, uint32_t src_bytes) {
    asm volatile("cp.async.cg.shared.global [%0], [%1], 16, %2;\n"
                 :: "r"(dst), "l"(src), "r"(src_bytes) : "memory");
}
__device__ __forceinline__ void cp_commit() {
    asm volatile("cp.async.commit_group;" ::: "memory");
}
__device__ __forceinline__ void cp_wait1() {
    asm volatile("cp.async.wait_group 1;" ::: "memory");
}

__device__ __forceinline__ void ldsm_x4(uint32_t& r0, uint32_t& r1, uint32_t& r2, uint32_t& r3,
                                        uint32_t addr) {
    asm volatile("ldmatrix.sync.aligned.m8n8.x4.shared.b16 {%0,%1,%2,%3}, [%4];"
                 : "=r"(r0), "=r"(r1), "=r"(r2), "=r"(r3) : "r"(addr));
}

__device__ __forceinline__ void ldsm_x4_t(uint32_t& r0, uint32_t& r1, uint32_t& r2, uint32_t& r3,
                                          uint32_t addr) {
    asm volatile("ldmatrix.sync.aligned.m8n8.x4.trans.shared.b16 {%0,%1,%2,%3}, [%4];"
                 : "=r"(r0), "=r"(r1), "=r"(r2), "=r"(r3) : "r"(addr));
}

__device__ __forceinline__ void mma_f16_k16(float* c, const uint32_t* a, uint32_t b0, uint32_t b1) {
    asm volatile(
        "mma.sync.aligned.m16n8k16.row.col.f32.f16.f16.f32 "
        "{%0,%1,%2,%3}, {%4,%5,%6,%7}, {%8,%9}, {%0,%1,%2,%3};\n"
        : "+f"(c[0]), "+f"(c[1]), "+f"(c[2]), "+f"(c[3])
        : "r"(a[0]), "r"(a[1]), "r"(a[2]), "r"(a[3]), "r"(b0), "r"(b1));
}

// Fetch expert id for assignment i, handling int32 vs int64 wire format.
__device__ __forceinline__ int get_expert(const int* se32, int i) {
    int v = g_is64 ? se32[2 * i] : se32[i];   // little-endian low word for int64
    return v & (NEXP - 1);
}

// ---------------- prep: zero out + convert x + dtype detection (fused) ----------------
__global__ void prep_kernel(float4* __restrict__ out, const float4* __restrict__ x,
                            const int* __restrict__ se32, int n4) {
    int i = blockIdx.x * blockDim.x + threadIdx.x;
    if (blockIdx.x == 0 && threadIdx.x == 0) {
        int nz = 0;
        #pragma unroll 8
        for (int j = 1; j < 256; j += 2) nz |= se32[j];
        g_is64 = (nz == 0) ? 1 : 0;
    }
    if (i < n4) {
        out[i] = make_float4(0.f, 0.f, 0.f, 0.f);
        float4 v = x[i];
        uint2 u;
        u.x = h2_bits(__floats2half2_rn(v.x, v.y));
        u.y = h2_bits(__floats2half2_rn(v.z, v.w));
        ((uint2*)g_xh)[i] = u;
    }
}

// ---------------- f32 -> f16 conversion pass for weights ----------------
__global__ void conv_half_kernel(const float4* __restrict__ in, uint2* __restrict__ outp, int n4) {
    int i = blockIdx.x * blockDim.x + threadIdx.x;
    if (i < n4) {
        float4 v = in[i];
        uint2 u;
        u.x = h2_bits(__floats2half2_rn(v.x, v.y));
        u.y = h2_bits(__floats2half2_rn(v.z, v.w));
        outp[i] = u;
    }
}

// ---------------- routing: warp-per-expert ballot scan (deterministic, stable) ----------------
__global__ void route_kernel(const int* __restrict__ se32, const float* __restrict__ rw) {
    const int tid  = threadIdx.x;
    const int warp = tid >> 5;          // warp w owns expert w
    const int lane = tid & 31;
    const unsigned lt = (1u << lane) - 1u;

    int cnt = 0;
    for (int it = 0; it < NASN / 32; it++) {
        int i = it * 32 + lane;
        unsigned m = __ballot_sync(0xFFFFFFFFu, get_expert(se32, i) == warp);
        cnt += __popc(m);
    }
    if (lane == 0) g_count[warp] = cnt;
    __syncthreads();
    if (tid == 0) {
        int off = 0;
        for (int e = 0; e < NEXP; e++) { g_offset[e] = off; off += g_count[e]; }
    }
    __syncthreads();

    int base = g_offset[warp];
    for (int it = 0; it < NASN / 32; it++) {
        int i = it * 32 + lane;
        bool mine = (get_expert(se32, i) == warp);
        unsigned m = __ballot_sync(0xFFFFFFFFu, mine);
        if (mine) {
            int r = __popc(m & lt);
            g_tok[base + r] = i / KTOP;
            g_wt[base + r]  = rw[i];
        }
        base += __popc(m);
    }
}

// ---------------- grouped GEMM (fp16 mma m16n8k16 + ldmatrix, 128x128x32, cp.async 3-stage) ----------------
// SECOND == false : g_h = half(silu(gather(g_xh) @ g_w1h))
// SECOND == true  : out[tok] += (g_h @ g_w2h) * wt  (atomicAdd)
template <int KDIM, int NDIM, bool SECOND>
__global__ __launch_bounds__(256)
void moe_gemm(float* __restrict__ Oglob) {
    constexpr int BM = 128, BN = 128, BK = 32;
    constexpr int ASTR = 40;    // halves per A row
    constexpr int BSTR = 136;   // halves per B row
    constexpr int NSTAGE = 3;
    constexpr int A_HALVES = BM * ASTR;                  // 5120
    constexpr int STAGE_H  = A_HALVES + BK * BSTR;       // 9472 halves = 18944 B
    constexpr int NKB      = KDIM / BK;

    extern __shared__ __half sh[];
    const uint32_t sb = smem_u32(sh);

    const __half* Ain  = SECOND ? g_h : g_xh;
    const __half* Wall = SECOND ? g_w2h : g_w1h;

    const int e   = blockIdx.z;
    const int cnt = g_count[e];
    if ((int)blockIdx.y * BM >= cnt) return;

    const int off     = g_offset[e];
    const int rowBase = off + blockIdx.y * BM;
    const int rowEnd  = off + cnt;
    const int nBase   = blockIdx.x * BN;
    const __half* Wp  = Wall + (size_t)e * KDIM * NDIM;

    const int tid  = threadIdx.x;
    const int lane = tid & 31;
    const int warp = tid >> 5;
    const int gq   = lane >> 2;          // groupID 0..7
    const int tig  = lane & 3;           // thread-in-group 0..3
    const int wm   = (warp >> 1) * 32;   // 4 warp-rows of 32
    const int wn   = (warp & 1) * 64;    // 2 warp-cols of 64

    // ldmatrix per-lane addressing
    const int lg = lane >> 3;
    const int lr = lane & 7;
    const int mrow_off = ((lg & 1) ? 8 : 0) + lr;
    const int kcol_off = (lg >= 2) ? 8 : 0;

    // ---- copy plans (uint4 = 8 halves, cp.async 16B) ----
    const __half* asrc[2]; uint32_t adst[2]; uint32_t abytes[2];
    #pragma unroll
    for (int j = 0; j < 2; j++) {
        int chunk = tid + j * 256;
        int r = chunk >> 2, c8 = (chunk & 3) * 8;
        adst[j] = (uint32_t)(r * ASTR + c8) * 2u;
        int grow = rowBase + r;
        bool v = (grow < rowEnd);
        abytes[j] = v ? 16u : 0u;
        asrc[j] = v ? (Ain + (size_t)(SECOND ? grow : g_tok[grow]) * KDIM + c8) : Ain;
    }
    const __half* bsrc[2]; uint32_t bdst[2];
    #pragma unroll
    for (int j = 0; j < 2; j++) {
        int chunk = tid + j * 256;
        int k = chunk >> 4, c8 = (chunk & 15) * 8;
        bdst[j] = (uint32_t)(A_HALVES + k * BSTR + c8) * 2u;
        bsrc[j] = Wp + (size_t)k * NDIM + nBase + c8;
    }

    auto load_stage = [&](int s, int kb) {
        const uint32_t sbase = sb + (uint32_t)s * (STAGE_H * 2);
        const int koff = kb * BK;
        #pragma unroll
        for (int j = 0; j < 2; j++) cp_async16(sbase + adst[j], asrc[j] + koff, abytes[j]);
        #pragma unroll
        for (int j = 0; j < 2; j++) cp_async16(sbase + bdst[j], bsrc[j] + (size_t)koff * NDIM, 16u);
    };

    float acc[2][8][4];
    #pragma unroll
    for (int mt = 0; mt < 2; mt++)
        #pragma unroll
        for (int nt = 0; nt < 8; nt++)
            #pragma unroll
            for (int q = 0; q < 4; q++) acc[mt][nt][q] = 0.f;

    auto compute = [&](int s) {
        const uint32_t abase = sb + (uint32_t)s * (STAGE_H * 2);
        const uint32_t bbase = abase + (uint32_t)(A_HALVES * 2);
        #pragma unroll
        for (int ks = 0; ks < 2; ks++) {
            const int k0 = ks * 16;
            uint32_t a[2][4];
            #pragma unroll
            for (int mt = 0; mt < 2; mt++) {
                uint32_t addr = abase +
                    (uint32_t)((wm + mt * 16 + mrow_off) * ASTR + k0 + kcol_off) * 2u;
                ldsm_x4(a[mt][0], a[mt][1], a[mt][2], a[mt][3], addr);
            }
            uint32_t b[4][4];
            #pragma unroll
            for (int nt2 = 0; nt2 < 4; nt2++) {
                uint32_t addr = bbase +
                    (uint32_t)((k0 + mrow_off) * BSTR + wn + nt2 * 16 + kcol_off) * 2u;
                ldsm_x4_t(b[nt2][0], b[nt2][1], b[nt2][2], b[nt2][3], addr);
            }
            #pragma unroll
            for (int nt2 = 0; nt2 < 4; nt2++) {
                mma_f16_k16(acc[0][2 * nt2],     a[0], b[nt2][0], b[nt2][1]);
                mma_f16_k16(acc[1][2 * nt2],     a[1], b[nt2][0], b[nt2][1]);
                mma_f16_k16(acc[0][2 * nt2 + 1], a[0], b[nt2][2], b[nt2][3]);
                mma_f16_k16(acc[1][2 * nt2 + 1], a[1], b[nt2][2], b[nt2][3]);
            }
        }
    };

    // prologue: stages for kb=0,1 in flight
    load_stage(0, 0); cp_commit();
    load_stage(1, 1); cp_commit();

    int s = 0;
    for (int kb = 0; kb < NKB; ++kb) {
        cp_wait1();            // group kb drained (at most group kb+1 pending)
        __syncthreads();       // data visible; also protects stage reuse below
        if (kb + 2 < NKB) load_stage((s + 2) % NSTAGE, kb + 2);
        cp_commit();           // always commit: keeps group count aligned in the tail
        compute(s);
        s = (s + 1) % NSTAGE;
    }

    // ---------------- epilogue (identical to R12) ----------------
    #pragma unroll
    for (int mt = 0; mt < 2; mt++) {
        #pragma unroll
        for (int half = 0; half < 2; half++) {
            int rloc = wm + mt * 16 + gq + half * 8;
            int grow = rowBase + rloc;
            if (grow >= rowEnd) continue;
            if (SECOND) {
                const int   tok = g_tok[grow];
                const float wgt = g_wt[grow];
                float* orow = Oglob + (size_t)tok * NDIM + nBase;
                #pragma unroll
                for (int nt = 0; nt < 8; nt++) {
                    int cc = wn + nt * 8 + tig * 2;
                    atomicAdd(&orow[cc],     acc[mt][nt][half * 2 + 0] * wgt);
                    atomicAdd(&orow[cc + 1], acc[mt][nt][half * 2 + 1] * wgt);
                }
            } else {
                __half* hrow = g_h + (size_t)grow * NDIM + nBase;
                #pragma unroll
                for (int nt = 0; nt < 8; nt++) {
                    int cc = wn + nt * 8 + tig * 2;
                    float v0 = acc[mt][nt][half * 2 + 0];
                    float v1 = acc[mt][nt][half * 2 + 1];
                    float s0 = v0 / (1.f + __expf(-v0));   // silu
                    float s1 = v1 / (1.f + __expf(-v1));
                    *(__half2*)(hrow + cc) = __floats2half2_rn(s0, s1);
                }
            }
        }
    }
}

// ---------------- launch ----------------
extern "C" void kernel_launch(void* const* d_in, const int* in_sizes, int n_in,
                              void* d_out, int out_size) {
    const float* x    = (const float*)d_in[0];
    const float* rw   = (const float*)d_in[1];
    const int*   se32 = (const int*)d_in[2];
    const float* w1   = (const float*)d_in[3];
    const float* w2   = (const float*)d_in[4];
    float*       out  = (float*)d_out;

    constexpr int SMEM_BYTES = 3 * ((128 * 40 + 32 * 136) * 2);  // 56832

    static void* p_w1h = nullptr;
    static void* p_w2h = nullptr;
    if (!p_w1h) {
        cudaGetSymbolAddress(&p_w1h, g_w1h);
        cudaGetSymbolAddress(&p_w2h, g_w2h);
        cudaFuncSetAttribute((const void*)moe_gemm<DDIM, IDIM, false>,
                             cudaFuncAttributeMaxDynamicSharedMemorySize, SMEM_BYTES);
        cudaFuncSetAttribute((const void*)moe_gemm<IDIM, DDIM, true>,
                             cudaFuncAttributeMaxDynamicSharedMemorySize, SMEM_BYTES);
    }

    int n4 = out_size / 4;                 // 1M float4 (out and x same size)
    int w4 = (NEXP * DDIM * IDIM) / 4;     // 4M float4 per weight tensor

    // 1: prep (zero out + convert x + dtype), 2: route, 3-4: weight conversions
    prep_kernel<<<(n4 + 255) / 256, 256>>>((float4*)out, (const float4*)x, se32, n4);
    route_kernel<<<1, 256>>>(se32, rw);
    conv_half_kernel<<<(w4 + 255) / 256, 256>>>((const float4*)w1, (uint2*)p_w1h, w4);
    conv_half_kernel<<<(w4 + 255) / 256, 256>>>((const float4*)w2, (uint2*)p_w2h, w4);

    // 5: GEMM1
    dim3 g1(IDIM / 128, NASN / 128, NEXP);   // (16, 64, 8)
    moe_gemm<DDIM, IDIM, false><<<g1, 256, SMEM_BYTES>>>(out);

    // 6: GEMM2 (ncu -s 5 -c 1 captures this)
    dim3 g2(DDIM / 128, NASN / 128, NEXP);   // (8, 64, 8)
    moe_gemm<IDIM, DDIM, true><<<g2, 256, SMEM_BYTES>>>(out);
}